// round 5
// baseline (speedup 1.0000x reference)
#include <cuda_runtime.h>

// Problem-shape maxima (fixed by the dataset)
#define NMAX   50000
#define EMAX   800000
#define ETMAX  (EMAX + NMAX)      // edges + self loops
#define HEADS  4
#define HC1    128                // heads * 32
#define HC2    256                // heads * 64
#define NEG_SLOPE 0.2f
#define GAT_EPS 1e-16f

// ---------------- scratch (static device globals; no allocation) ------------
__device__ float g_h1 [NMAX * HC1];   // layer1 linear output
__device__ float g_y1 [NMAX * HC1];   // layer1 output after elu (input of layer2)
__device__ float g_h2 [NMAX * HC2];   // layer2 linear output
__device__ float g_asrc[NMAX * HEADS];
__device__ float g_adst[NMAX * HEADS];
__device__ float g_e   [ETMAX * HEADS]; // exp(logit) per sorted-edge/head
__device__ int2  g_sd  [ETMAX];         // (src,dst) pairs incl self loops (orig order)
__device__ int2  g_ssd [ETMAX];         // pairs sorted by dst
__device__ int   g_cnt [NMAX + 1];      // histogram -> exclusive offsets
__device__ int   g_cur [NMAX + 1];      // placement cursors
__device__ int   g_is64;

// ---------------- helpers ---------------------------------------------------
__device__ __forceinline__ float lrelu(float x) {
    return x > 0.0f ? x : NEG_SLOPE * x;
}
__device__ __forceinline__ int eidx(const int* __restrict__ ei, int is64, long long pos) {
    if (is64) return (int)((const long long*)ei)[pos];
    return ei[pos];
}

// ---------------- dtype detection -------------------------------------------
__global__ void detect_kernel(const unsigned int* __restrict__ w, long long nWords) {
    __shared__ int s_nz;
    if (threadIdx.x == 0) s_nz = 0;
    __syncthreads();
    long long limit = nWords < 16384 ? nWords : 16384;
    int nz = 0;
    for (long long i = 1 + 2LL * threadIdx.x; i < limit; i += 2LL * blockDim.x)
        nz |= (w[i] != 0u);
    if (nz) atomicOr(&s_nz, 1);
    __syncthreads();
    if (threadIdx.x == 0) g_is64 = (s_nz == 0) ? 1 : 0;
}

// ---------------- build (src,dst) pairs + self loops, zero histogram --------
__global__ void prep_kernel(const int* __restrict__ ei, int E, int Nn,
                            int2* __restrict__ sd, int* __restrict__ cnt) {
    int e = blockIdx.x * blockDim.x + threadIdx.x;
    if (e <= Nn) cnt[e] = 0;
    int Et = E + Nn;
    if (e >= Et) return;
    int is64 = g_is64;
    int s, d;
    if (e < E) { s = eidx(ei, is64, e); d = eidx(ei, is64, (long long)E + e); }
    else       { s = d = e - E; }
    sd[e] = make_int2(s, d);
}

// ---------------- counting sort by dst --------------------------------------
__global__ void hist_kernel(const int2* __restrict__ sd, int Et, int* __restrict__ cnt) {
    int e = blockIdx.x * blockDim.x + threadIdx.x;
    if (e >= Et) return;
    atomicAdd(&cnt[sd[e].y], 1);
}

#define SCAN_T 1024
__global__ void scan_kernel(int* __restrict__ cnt, int* __restrict__ cur, int Nn) {
    __shared__ int ssum[SCAN_T];
    int t = threadIdx.x;
    int C = (Nn + SCAN_T - 1) / SCAN_T;
    int b = t * C;
    int local = 0;
    for (int i = 0; i < C; i++) if (b + i < Nn) local += cnt[b + i];
    ssum[t] = local;
    __syncthreads();
#pragma unroll
    for (int o = 1; o < SCAN_T; o <<= 1) {
        int v = (t >= o) ? ssum[t - o] : 0;
        __syncthreads();
        ssum[t] += v;
        __syncthreads();
    }
    int run = ssum[t] - local;                 // exclusive prefix
    for (int i = 0; i < C; i++) {
        if (b + i < Nn) {
            int c = cnt[b + i];
            cnt[b + i] = run;
            cur[b + i] = run;
            run += c;
        }
    }
    if (t == SCAN_T - 1) cnt[Nn] = run;        // total
}

__global__ void place_kernel(const int2* __restrict__ sd, int Et,
                             int* __restrict__ cur, int2* __restrict__ ssd) {
    int e = blockIdx.x * blockDim.x + threadIdx.x;
    if (e >= Et) return;
    int2 p = sd[e];
    int pos = atomicAdd(&cur[p.y], 1);
    ssd[pos] = p;
}

// ---------------- tiled GEMM: Y[M,NOUT] = X[M,128] @ W[128,NOUT] ------------
#define XPAD 132
template<int NOUT>
__global__ void gemm_tiled(const float* __restrict__ X,
                           const float* __restrict__ W,
                           float* __restrict__ Y, int M) {
    extern __shared__ float smem[];
    float (*Xs)[XPAD] = (float (*)[XPAD])smem;                 // [64][132]
    float (*Ws)[128]  = (float (*)[128])(smem + 64 * XPAD);    // [128][128]

    const int row0 = blockIdx.x * 64;
    const int c0   = blockIdx.y * 128;
    const int tid  = threadIdx.x;

#pragma unroll
    for (int i = 0; i < 8; i++) {
        int idx = tid + i * 256;
        int r = idx >> 5, kq = idx & 31;
        float4 v = (row0 + r < M) ? ((const float4*)X)[(size_t)(row0 + r) * 32 + kq]
                                  : make_float4(0.f, 0.f, 0.f, 0.f);
        *(float4*)&Xs[r][kq * 4] = v;
    }
#pragma unroll
    for (int i = 0; i < 16; i++) {
        int idx = tid + i * 256;
        int k = idx >> 5, cq = idx & 31;
        *(float4*)&Ws[k][cq * 4] =
            *(const float4*)&W[(size_t)k * NOUT + c0 + cq * 4];
    }
    __syncthreads();

    const int tx = tid & 15, ty = tid >> 4;
    float acc[4][8];
#pragma unroll
    for (int ri = 0; ri < 4; ri++)
#pragma unroll
        for (int ci = 0; ci < 8; ci++) acc[ri][ci] = 0.0f;

#pragma unroll 4
    for (int k = 0; k < 128; k++) {
        float4 w0 = *(float4*)&Ws[k][tx * 8];
        float4 w1 = *(float4*)&Ws[k][tx * 8 + 4];
        float xv[4];
#pragma unroll
        for (int ri = 0; ri < 4; ri++) xv[ri] = Xs[ty * 4 + ri][k];
#pragma unroll
        for (int ri = 0; ri < 4; ri++) {
            acc[ri][0] = fmaf(xv[ri], w0.x, acc[ri][0]);
            acc[ri][1] = fmaf(xv[ri], w0.y, acc[ri][1]);
            acc[ri][2] = fmaf(xv[ri], w0.z, acc[ri][2]);
            acc[ri][3] = fmaf(xv[ri], w0.w, acc[ri][3]);
            acc[ri][4] = fmaf(xv[ri], w1.x, acc[ri][4]);
            acc[ri][5] = fmaf(xv[ri], w1.y, acc[ri][5]);
            acc[ri][6] = fmaf(xv[ri], w1.z, acc[ri][6]);
            acc[ri][7] = fmaf(xv[ri], w1.w, acc[ri][7]);
        }
    }

#pragma unroll
    for (int ri = 0; ri < 4; ri++) {
        int r = row0 + ty * 4 + ri;
        if (r < M) {
            float4 o0 = make_float4(acc[ri][0], acc[ri][1], acc[ri][2], acc[ri][3]);
            float4 o1 = make_float4(acc[ri][4], acc[ri][5], acc[ri][6], acc[ri][7]);
            *(float4*)&Y[(size_t)r * NOUT + c0 + tx * 8]     = o0;
            *(float4*)&Y[(size_t)r * NOUT + c0 + tx * 8 + 4] = o1;
        }
    }
}
#define GEMM_SMEM ((64 * XPAD + 128 * 128) * 4)

// ---------------- per-node attention coefficients (warp per node) -----------
// lane L covers 8 consecutive channels (2 float4 for HC2, 1 float4 +
// neighbor-pair for HC1); 8-lane groups map exactly to one head.
template<int HC>
__global__ void att_kernel(const float* __restrict__ H,
                           const float* __restrict__ av_src,
                           const float* __restrict__ av_dst,
                           float* __restrict__ osrc,
                           float* __restrict__ odst, int Nn) {
    const int w    = threadIdx.x >> 5;
    const int lane = threadIdx.x & 31;
    const int n    = blockIdx.x * 8 + w;
    if (n >= Nn) return;
    constexpr int NV = HC / 128;            // float4 per lane: 1 (HC1) or 2 (HC2)
    const float4* h4 = (const float4*)(H + (size_t)n * HC);
    const float4* s4 = (const float4*)av_src;
    const float4* d4 = (const float4*)av_dst;
    float ps = 0.f, pd = 0.f;
#pragma unroll
    for (int v = 0; v < NV; v++) {
        int i = lane * NV + v;
        float4 h = h4[i], a = s4[i], b = d4[i];
        ps += h.x * a.x + h.y * a.y + h.z * a.z + h.w * a.w;
        pd += h.x * b.x + h.y * b.y + h.z * b.z + h.w * b.w;
    }
    // reduce within 8-lane groups (one head per group)
#pragma unroll
    for (int o = 4; o > 0; o >>= 1) {
        ps += __shfl_down_sync(0xffffffffu, ps, o);
        pd += __shfl_down_sync(0xffffffffu, pd, o);
    }
    if ((lane & 7) == 0) {
        int h = lane >> 3;
        osrc[n * HEADS + h] = ps;
        odst[n * HEADS + h] = pd;
    }
}

// ---------------- edge pass: ev = exp(lrelu(asrc+adst)) over sorted edges ---
__global__ void edge_exp_kernel(const int2* __restrict__ ssd, int Et,
                                const float* __restrict__ asrc,
                                const float* __restrict__ adst,
                                float* __restrict__ ebuf) {
    int e = blockIdx.x * blockDim.x + threadIdx.x;
    if (e >= Et) return;
    int2 p = ssd[e];
    float4 as = ((const float4*)asrc)[p.x];
    float4 ad = ((const float4*)adst)[p.y];
    float4 ev;
    ev.x = expf(lrelu(as.x + ad.x));
    ev.y = expf(lrelu(as.y + ad.y));
    ev.z = expf(lrelu(as.z + ad.z));
    ev.w = expf(lrelu(as.w + ad.w));
    ((float4*)ebuf)[e] = ev;
}

// ---------------- gather-reduce: block per dst node -------------------------
// MODE 0: layer1 epilogue (bias + elu) -> Y[n*HC + t]
// MODE 1: layer2 epilogue (head mean + bias) -> Y[n*64 + c]
template<int HC, int MODE>
__global__ void gather_reduce(const int2* __restrict__ ssd,
                              const int*  __restrict__ off,
                              const float* __restrict__ H,
                              const float* __restrict__ ebuf,
                              const float* __restrict__ bias,
                              float* __restrict__ Y) {
    const int n = blockIdx.x;
    const int t = threadIdx.x;
    constexpr int CH = HC / HEADS;
    const int head = t / CH;

    int pos = off[n];
    const int end = off[n + 1];

    float acc = 0.f, sume = 0.f;
    // software pipeline: prefetch next (src, ev)
    int   src_n = ssd[pos].x;
    float ev_n  = __ldg(&ebuf[pos * 4 + head]);
    while (pos < end) {
        int   src = src_n;
        float ev  = ev_n;
        int nx = pos + 1;
        if (nx < end) {
            src_n = ssd[nx].x;
            ev_n  = __ldg(&ebuf[nx * 4 + head]);
        }
        acc  = fmaf(ev, __ldg(&H[(size_t)src * HC + t]), acc);
        sume += ev;
        pos = nx;
    }

    __shared__ float s_inv[HEADS];
    __shared__ float s_val[HC];
    if ((t & (CH - 1)) == 0) s_inv[head] = 1.0f / (sume + GAT_EPS);
    __syncthreads();
    float v = acc * s_inv[head];

    if (MODE == 0) {
        v += bias[t];
        Y[(size_t)n * HC + t] = v > 0.0f ? v : expm1f(v);
    } else {
        s_val[t] = v;
        __syncthreads();
        if (t < 64)
            Y[(size_t)n * 64 + t] =
                0.25f * (s_val[t] + s_val[t + 64] + s_val[t + 128] + s_val[t + 192])
                + bias[t];
    }
}

// ---------------- launch ----------------------------------------------------
extern "C" void kernel_launch(void* const* d_in, const int* in_sizes, int n_in,
                              void* d_out, int out_size) {
    const float* x    = (const float*)d_in[0];
    const int*   ei   = (const int*)d_in[1];
    const float* W1   = (const float*)d_in[2];
    const float* as1  = (const float*)d_in[3];
    const float* ad1  = (const float*)d_in[4];
    const float* b1   = (const float*)d_in[5];
    const float* W2   = (const float*)d_in[6];
    const float* as2  = (const float*)d_in[7];
    const float* ad2  = (const float*)d_in[8];
    const float* b2   = (const float*)d_in[9];
    float*       out  = (float*)d_out;

    const int N  = in_sizes[0] / 128;
    const int E  = in_sizes[1] / 2;
    const int Et = E + N;

    float *p_h1, *p_y1, *p_h2, *p_as, *p_ad, *p_e;
    int2 *p_sd, *p_ssd;
    int *p_cnt, *p_cur;
    cudaGetSymbolAddress((void**)&p_h1,  g_h1);
    cudaGetSymbolAddress((void**)&p_y1,  g_y1);
    cudaGetSymbolAddress((void**)&p_h2,  g_h2);
    cudaGetSymbolAddress((void**)&p_as,  g_asrc);
    cudaGetSymbolAddress((void**)&p_ad,  g_adst);
    cudaGetSymbolAddress((void**)&p_e,   g_e);
    cudaGetSymbolAddress((void**)&p_sd,  g_sd);
    cudaGetSymbolAddress((void**)&p_ssd, g_ssd);
    cudaGetSymbolAddress((void**)&p_cnt, g_cnt);
    cudaGetSymbolAddress((void**)&p_cur, g_cur);

    static int smem_set = 0;
    if (!smem_set) {
        cudaFuncSetAttribute(gemm_tiled<HC1>, cudaFuncAttributeMaxDynamicSharedMemorySize, GEMM_SMEM);
        cudaFuncSetAttribute(gemm_tiled<HC2>, cudaFuncAttributeMaxDynamicSharedMemorySize, GEMM_SMEM);
        smem_set = 1;
    }

    const int TB = 256;
    const int gemmRows = (N + 63) / 64;
    const int attGrid  = (N + 7) / 8;

    // ---- edge preprocessing: dtype sniff + counting sort by dst ----
    detect_kernel<<<1, 256>>>((const unsigned int*)ei, (long long)in_sizes[1] * 2);
    prep_kernel<<<(Et + TB - 1) / TB, TB>>>(ei, E, N, p_sd, p_cnt);
    hist_kernel<<<(Et + TB - 1) / TB, TB>>>(p_sd, Et, p_cnt);
    scan_kernel<<<1, SCAN_T>>>(p_cnt, p_cur, N);
    place_kernel<<<(Et + TB - 1) / TB, TB>>>(p_sd, Et, p_cur, p_ssd);

    // ===== Layer 1 =====
    gemm_tiled<HC1><<<dim3(gemmRows, 1), 256, GEMM_SMEM>>>(x, W1, p_h1, N);
    att_kernel<HC1><<<attGrid, 256>>>(p_h1, as1, ad1, p_as, p_ad, N);
    edge_exp_kernel<<<(Et + TB - 1) / TB, TB>>>(p_ssd, Et, p_as, p_ad, p_e);
    gather_reduce<HC1, 0><<<N, HC1>>>(p_ssd, p_cnt, p_h1, p_e, b1, p_y1);

    // ===== Layer 2 =====
    gemm_tiled<HC2><<<dim3(gemmRows, 2), 256, GEMM_SMEM>>>(p_y1, W2, p_h2, N);
    att_kernel<HC2><<<attGrid, 256>>>(p_h2, as2, ad2, p_as, p_ad, N);
    edge_exp_kernel<<<(Et + TB - 1) / TB, TB>>>(p_ssd, Et, p_as, p_ad, p_e);
    gather_reduce<HC2, 1><<<N, HC2>>>(p_ssd, p_cnt, p_h2, p_e, b2, out);
}

// round 6
// speedup vs baseline: 2.4468x; 2.4468x over previous
#include <cuda_runtime.h>

// Problem-shape maxima (fixed by the dataset)
#define NMAX   50000
#define EMAX   800000
#define ETMAX  (EMAX + NMAX)      // edges + self loops
#define HEADS  4
#define HC1    128                // heads * 32
#define HC2    256                // heads * 64
#define NEG_SLOPE 0.2f
#define GAT_EPS 1e-16f
#define CHUNK  256

// ---------------- scratch (static device globals; no allocation) ------------
__device__ float g_h1 [NMAX * HC1];
__device__ float g_y1 [NMAX * HC1];
__device__ float g_h2 [NMAX * HC2];
__device__ float g_asrc[NMAX * HEADS];
__device__ float g_adst[NMAX * HEADS];
__device__ float g_e   [ETMAX * HEADS];
__device__ int2  g_sd  [ETMAX];
__device__ int2  g_ssd [ETMAX];
__device__ int   g_cnt [NMAX + 1];
__device__ int   g_cur [NMAX + 1];
__device__ int   g_part[CHUNK];
__device__ int   g_is64;

// ---------------- helpers ---------------------------------------------------
__device__ __forceinline__ float lrelu(float x) {
    return x > 0.0f ? x : NEG_SLOPE * x;
}
__device__ __forceinline__ int eidx(const int* __restrict__ ei, int is64, long long pos) {
    if (is64) return (int)((const long long*)ei)[pos];
    return ei[pos];
}
__device__ __forceinline__ void fma4(float4& a, float s, float4 v) {
    a.x = fmaf(s, v.x, a.x); a.y = fmaf(s, v.y, a.y);
    a.z = fmaf(s, v.z, a.z); a.w = fmaf(s, v.w, a.w);
}

// ---------------- dtype detection -------------------------------------------
__global__ void detect_kernel(const unsigned int* __restrict__ w, long long nWords) {
    __shared__ int s_nz;
    if (threadIdx.x == 0) s_nz = 0;
    __syncthreads();
    long long limit = nWords < 16384 ? nWords : 16384;
    int nz = 0;
    for (long long i = 1 + 2LL * threadIdx.x; i < limit; i += 2LL * blockDim.x)
        nz |= (w[i] != 0u);
    if (nz) atomicOr(&s_nz, 1);
    __syncthreads();
    if (threadIdx.x == 0) g_is64 = (s_nz == 0) ? 1 : 0;
}

// ---------------- build (src,dst) pairs + self loops, zero histogram --------
__global__ void prep_kernel(const int* __restrict__ ei, int E, int Nn,
                            int2* __restrict__ sd, int* __restrict__ cnt) {
    int e = blockIdx.x * blockDim.x + threadIdx.x;
    if (e <= Nn) cnt[e] = 0;
    int Et = E + Nn;
    if (e >= Et) return;
    int is64 = g_is64;
    int s, d;
    if (e < E) { s = eidx(ei, is64, e); d = eidx(ei, is64, (long long)E + e); }
    else       { s = d = e - E; }
    sd[e] = make_int2(s, d);
}

// ---------------- counting sort by dst --------------------------------------
__global__ void hist_kernel(const int2* __restrict__ sd, int Et, int* __restrict__ cnt) {
    int e = blockIdx.x * blockDim.x + threadIdx.x;
    if (e >= Et) return;
    atomicAdd(&cnt[sd[e].y], 1);
}

// 3-phase parallel exclusive scan over cnt[0..Nn)
__global__ void scan_partial(const int* __restrict__ cnt, int* __restrict__ part, int Nn) {
    __shared__ int s[CHUNK];
    int i = blockIdx.x * CHUNK + threadIdx.x;
    s[threadIdx.x] = (i < Nn) ? cnt[i] : 0;
    __syncthreads();
#pragma unroll
    for (int o = CHUNK / 2; o > 0; o >>= 1) {
        if (threadIdx.x < o) s[threadIdx.x] += s[threadIdx.x + o];
        __syncthreads();
    }
    if (threadIdx.x == 0) part[blockIdx.x] = s[0];
}
__global__ void scan_tops(int* __restrict__ part, int nb, int* __restrict__ cnt, int Nn) {
    __shared__ int s[CHUNK];
    int t = threadIdx.x;
    int v = (t < nb) ? part[t] : 0;
    s[t] = v;
    __syncthreads();
#pragma unroll
    for (int o = 1; o < CHUNK; o <<= 1) {
        int u = (t >= o) ? s[t - o] : 0;
        __syncthreads();
        s[t] += u;
        __syncthreads();
    }
    if (t < nb) part[t] = s[t] - v;            // exclusive block base
    if (t == CHUNK - 1) cnt[Nn] = s[CHUNK - 1]; // total edges
}
__global__ void scan_final(int* __restrict__ cnt, int* __restrict__ cur,
                           const int* __restrict__ part, int Nn) {
    __shared__ int s[CHUNK];
    int i = blockIdx.x * CHUNK + threadIdx.x;
    int t = threadIdx.x;
    int v = (i < Nn) ? cnt[i] : 0;
    s[t] = v;
    __syncthreads();
#pragma unroll
    for (int o = 1; o < CHUNK; o <<= 1) {
        int u = (t >= o) ? s[t - o] : 0;
        __syncthreads();
        s[t] += u;
        __syncthreads();
    }
    if (i < Nn) {
        int ex = part[blockIdx.x] + s[t] - v;
        cnt[i] = ex;
        cur[i] = ex;
    }
}

__global__ void place_kernel(const int2* __restrict__ sd, int Et,
                             int* __restrict__ cur, int2* __restrict__ ssd) {
    int e = blockIdx.x * blockDim.x + threadIdx.x;
    if (e >= Et) return;
    int2 p = sd[e];
    int pos = atomicAdd(&cur[p.y], 1);
    ssd[pos] = p;
}

// ---------------- tiled GEMM: Y[M,NOUT] = X[M,128] @ W[128,NOUT] ------------
#define XPAD 132
template<int NOUT>
__global__ void gemm_tiled(const float* __restrict__ X,
                           const float* __restrict__ W,
                           float* __restrict__ Y, int M) {
    extern __shared__ float smem[];
    float (*Xs)[XPAD] = (float (*)[XPAD])smem;                 // [64][132]
    float (*Ws)[128]  = (float (*)[128])(smem + 64 * XPAD);    // [128][128]

    const int row0 = blockIdx.x * 64;
    const int c0   = blockIdx.y * 128;
    const int tid  = threadIdx.x;

#pragma unroll
    for (int i = 0; i < 8; i++) {
        int idx = tid + i * 256;
        int r = idx >> 5, kq = idx & 31;
        float4 v = (row0 + r < M) ? ((const float4*)X)[(size_t)(row0 + r) * 32 + kq]
                                  : make_float4(0.f, 0.f, 0.f, 0.f);
        *(float4*)&Xs[r][kq * 4] = v;
    }
#pragma unroll
    for (int i = 0; i < 16; i++) {
        int idx = tid + i * 256;
        int k = idx >> 5, cq = idx & 31;
        *(float4*)&Ws[k][cq * 4] =
            *(const float4*)&W[(size_t)k * NOUT + c0 + cq * 4];
    }
    __syncthreads();

    const int tx = tid & 15, ty = tid >> 4;
    float acc[4][8];
#pragma unroll
    for (int ri = 0; ri < 4; ri++)
#pragma unroll
        for (int ci = 0; ci < 8; ci++) acc[ri][ci] = 0.0f;

#pragma unroll 4
    for (int k = 0; k < 128; k++) {
        float4 w0 = *(float4*)&Ws[k][tx * 8];
        float4 w1 = *(float4*)&Ws[k][tx * 8 + 4];
        float xv[4];
#pragma unroll
        for (int ri = 0; ri < 4; ri++) xv[ri] = Xs[ty * 4 + ri][k];
#pragma unroll
        for (int ri = 0; ri < 4; ri++) {
            acc[ri][0] = fmaf(xv[ri], w0.x, acc[ri][0]);
            acc[ri][1] = fmaf(xv[ri], w0.y, acc[ri][1]);
            acc[ri][2] = fmaf(xv[ri], w0.z, acc[ri][2]);
            acc[ri][3] = fmaf(xv[ri], w0.w, acc[ri][3]);
            acc[ri][4] = fmaf(xv[ri], w1.x, acc[ri][4]);
            acc[ri][5] = fmaf(xv[ri], w1.y, acc[ri][5]);
            acc[ri][6] = fmaf(xv[ri], w1.z, acc[ri][6]);
            acc[ri][7] = fmaf(xv[ri], w1.w, acc[ri][7]);
        }
    }

#pragma unroll
    for (int ri = 0; ri < 4; ri++) {
        int r = row0 + ty * 4 + ri;
        if (r < M) {
            float4 o0 = make_float4(acc[ri][0], acc[ri][1], acc[ri][2], acc[ri][3]);
            float4 o1 = make_float4(acc[ri][4], acc[ri][5], acc[ri][6], acc[ri][7]);
            *(float4*)&Y[(size_t)r * NOUT + c0 + tx * 8]     = o0;
            *(float4*)&Y[(size_t)r * NOUT + c0 + tx * 8 + 4] = o1;
        }
    }
}
#define GEMM_SMEM ((64 * XPAD + 128 * 128) * 4)

// ---------------- per-node attention coefficients (warp per node) -----------
template<int HC>
__global__ void att_kernel(const float* __restrict__ H,
                           const float* __restrict__ av_src,
                           const float* __restrict__ av_dst,
                           float* __restrict__ osrc,
                           float* __restrict__ odst, int Nn) {
    const int w    = threadIdx.x >> 5;
    const int lane = threadIdx.x & 31;
    const int n    = blockIdx.x * 8 + w;
    if (n >= Nn) return;
    constexpr int NV = HC / 128;
    const float4* h4 = (const float4*)(H + (size_t)n * HC);
    const float4* s4 = (const float4*)av_src;
    const float4* d4 = (const float4*)av_dst;
    float ps = 0.f, pd = 0.f;
#pragma unroll
    for (int v = 0; v < NV; v++) {
        int i = lane * NV + v;
        float4 h = h4[i], a = s4[i], b = d4[i];
        ps += h.x * a.x + h.y * a.y + h.z * a.z + h.w * a.w;
        pd += h.x * b.x + h.y * b.y + h.z * b.z + h.w * b.w;
    }
#pragma unroll
    for (int o = 4; o > 0; o >>= 1) {
        ps += __shfl_down_sync(0xffffffffu, ps, o);
        pd += __shfl_down_sync(0xffffffffu, pd, o);
    }
    if ((lane & 7) == 0) {
        int h = lane >> 3;
        osrc[n * HEADS + h] = ps;
        odst[n * HEADS + h] = pd;
    }
}

// ---------------- edge pass: ev = exp(lrelu(asrc+adst)) over sorted edges ---
__global__ void edge_exp_kernel(const int2* __restrict__ ssd, int Et,
                                const float* __restrict__ asrc,
                                const float* __restrict__ adst,
                                float* __restrict__ ebuf) {
    int e = blockIdx.x * blockDim.x + threadIdx.x;
    if (e >= Et) return;
    int2 p = ssd[e];
    float4 as = ((const float4*)asrc)[p.x];
    float4 ad = ((const float4*)adst)[p.y];
    float4 ev;
    ev.x = expf(lrelu(as.x + ad.x));
    ev.y = expf(lrelu(as.y + ad.y));
    ev.z = expf(lrelu(as.z + ad.z));
    ev.w = expf(lrelu(as.w + ad.w));
    ((float4*)ebuf)[e] = ev;
}

// ---------------- warp-per-node gather-reduce -------------------------------
// Lane L covers NV float4s (channels [L*NV*4, (L+1)*NV*4)), head = L/8.
// MODE 0: bias + elu -> Y[n*HC]    MODE 1: head-mean + bias -> Y[n*64]
template<int HC, int MODE>
__global__ void gather_warp(const int2* __restrict__ ssd,
                            const int*  __restrict__ off,
                            const float* __restrict__ H,
                            const float* __restrict__ ebuf,
                            const float* __restrict__ bias,
                            float* __restrict__ Y, int Nn) {
    const int n = (blockIdx.x * blockDim.x + threadIdx.x) >> 5;
    if (n >= Nn) return;
    const int lane = threadIdx.x & 31;
    const int head = lane >> 3;
    constexpr int NV = HC / 128;

    int pos = off[n];
    const int end = off[n + 1];

    float4 acc[NV];
#pragma unroll
    for (int v = 0; v < NV; v++) acc[v] = make_float4(0.f, 0.f, 0.f, 0.f);
    float sume = 0.f;

    // 4-wide unroll: 4 independent gathers in flight
    for (; pos + 4 <= end; pos += 4) {
        int s0 = ssd[pos].x, s1 = ssd[pos + 1].x, s2 = ssd[pos + 2].x, s3 = ssd[pos + 3].x;
        float e0 = __ldg(&ebuf[(pos    ) * 4 + head]);
        float e1 = __ldg(&ebuf[(pos + 1) * 4 + head]);
        float e2 = __ldg(&ebuf[(pos + 2) * 4 + head]);
        float e3 = __ldg(&ebuf[(pos + 3) * 4 + head]);
        const float4* h0 = (const float4*)(H + (size_t)s0 * HC);
        const float4* h1 = (const float4*)(H + (size_t)s1 * HC);
        const float4* h2 = (const float4*)(H + (size_t)s2 * HC);
        const float4* h3 = (const float4*)(H + (size_t)s3 * HC);
#pragma unroll
        for (int v = 0; v < NV; v++) {
            int i = lane * NV + v;
            float4 a0 = h0[i], a1 = h1[i], a2 = h2[i], a3 = h3[i];
            fma4(acc[v], e0, a0);
            fma4(acc[v], e1, a1);
            fma4(acc[v], e2, a2);
            fma4(acc[v], e3, a3);
        }
        sume += (e0 + e1) + (e2 + e3);
    }
    for (; pos < end; pos++) {
        int s0 = ssd[pos].x;
        float e0 = __ldg(&ebuf[pos * 4 + head]);
        const float4* h0 = (const float4*)(H + (size_t)s0 * HC);
#pragma unroll
        for (int v = 0; v < NV; v++) fma4(acc[v], e0, h0[lane * NV + v]);
        sume += e0;
    }

    const float inv = 1.0f / (sume + GAT_EPS);

    if (MODE == 0) {
        float4 v = acc[0];
        float4 b4 = ((const float4*)bias)[lane];
        v.x = v.x * inv + b4.x; v.y = v.y * inv + b4.y;
        v.z = v.z * inv + b4.z; v.w = v.w * inv + b4.w;
        v.x = v.x > 0.f ? v.x : expm1f(v.x);
        v.y = v.y > 0.f ? v.y : expm1f(v.y);
        v.z = v.z > 0.f ? v.z : expm1f(v.z);
        v.w = v.w > 0.f ? v.w : expm1f(v.w);
        ((float4*)(Y + (size_t)n * HC))[lane] = v;
    } else {
        float vv[8];
#pragma unroll
        for (int v = 0; v < NV; v++) {
            vv[v * 4 + 0] = acc[v].x * inv;
            vv[v * 4 + 1] = acc[v].y * inv;
            vv[v * 4 + 2] = acc[v].z * inv;
            vv[v * 4 + 3] = acc[v].w * inv;
        }
        // sum across 4 heads: lanes L, L+8, L+16, L+24 hold the same out-cols
#pragma unroll
        for (int j = 0; j < 8; j++) {
            vv[j] += __shfl_down_sync(0xffffffffu, vv[j], 16);
            vv[j] += __shfl_down_sync(0xffffffffu, vv[j], 8);
        }
        if (lane < 8) {
            float4 b0 = ((const float4*)bias)[lane * 2];
            float4 b1 = ((const float4*)bias)[lane * 2 + 1];
            float4 o0 = make_float4(0.25f * vv[0] + b0.x, 0.25f * vv[1] + b0.y,
                                    0.25f * vv[2] + b0.z, 0.25f * vv[3] + b0.w);
            float4 o1 = make_float4(0.25f * vv[4] + b1.x, 0.25f * vv[5] + b1.y,
                                    0.25f * vv[6] + b1.z, 0.25f * vv[7] + b1.w);
            float* yp = Y + (size_t)n * 64 + lane * 8;
            *(float4*)yp = o0;
            *(float4*)(yp + 4) = o1;
        }
    }
}

// ---------------- launch ----------------------------------------------------
extern "C" void kernel_launch(void* const* d_in, const int* in_sizes, int n_in,
                              void* d_out, int out_size) {
    const float* x    = (const float*)d_in[0];
    const int*   ei   = (const int*)d_in[1];
    const float* W1   = (const float*)d_in[2];
    const float* as1  = (const float*)d_in[3];
    const float* ad1  = (const float*)d_in[4];
    const float* b1   = (const float*)d_in[5];
    const float* W2   = (const float*)d_in[6];
    const float* as2  = (const float*)d_in[7];
    const float* ad2  = (const float*)d_in[8];
    const float* b2   = (const float*)d_in[9];
    float*       out  = (float*)d_out;

    const int N  = in_sizes[0] / 128;
    const int E  = in_sizes[1] / 2;
    const int Et = E + N;

    float *p_h1, *p_y1, *p_h2, *p_as, *p_ad, *p_e;
    int2 *p_sd, *p_ssd;
    int *p_cnt, *p_cur, *p_part;
    cudaGetSymbolAddress((void**)&p_h1,  g_h1);
    cudaGetSymbolAddress((void**)&p_y1,  g_y1);
    cudaGetSymbolAddress((void**)&p_h2,  g_h2);
    cudaGetSymbolAddress((void**)&p_as,  g_asrc);
    cudaGetSymbolAddress((void**)&p_ad,  g_adst);
    cudaGetSymbolAddress((void**)&p_e,   g_e);
    cudaGetSymbolAddress((void**)&p_sd,  g_sd);
    cudaGetSymbolAddress((void**)&p_ssd, g_ssd);
    cudaGetSymbolAddress((void**)&p_cnt, g_cnt);
    cudaGetSymbolAddress((void**)&p_cur, g_cur);
    cudaGetSymbolAddress((void**)&p_part, g_part);

    static int smem_set = 0;
    if (!smem_set) {
        cudaFuncSetAttribute(gemm_tiled<HC1>, cudaFuncAttributeMaxDynamicSharedMemorySize, GEMM_SMEM);
        cudaFuncSetAttribute(gemm_tiled<HC2>, cudaFuncAttributeMaxDynamicSharedMemorySize, GEMM_SMEM);
        smem_set = 1;
    }

    const int TB = 256;
    const int gemmRows = (N + 63) / 64;
    const int attGrid  = (N + 7) / 8;
    const int nb       = (N + CHUNK - 1) / CHUNK;
    const int gwGrid   = (N * 32 + TB - 1) / TB;   // warp per node

    // ---- edge preprocessing: dtype sniff + counting sort by dst ----
    detect_kernel<<<1, 256>>>((const unsigned int*)ei, (long long)in_sizes[1] * 2);
    prep_kernel<<<(Et + TB - 1) / TB, TB>>>(ei, E, N, p_sd, p_cnt);
    hist_kernel<<<(Et + TB - 1) / TB, TB>>>(p_sd, Et, p_cnt);
    scan_partial<<<nb, CHUNK>>>(p_cnt, p_part, N);
    scan_tops<<<1, CHUNK>>>(p_part, nb, p_cnt, N);
    scan_final<<<nb, CHUNK>>>(p_cnt, p_cur, p_part, N);
    place_kernel<<<(Et + TB - 1) / TB, TB>>>(p_sd, Et, p_cur, p_ssd);

    // ===== Layer 1 =====
    gemm_tiled<HC1><<<dim3(gemmRows, 1), 256, GEMM_SMEM>>>(x, W1, p_h1, N);
    att_kernel<HC1><<<attGrid, 256>>>(p_h1, as1, ad1, p_as, p_ad, N);
    edge_exp_kernel<<<(Et + TB - 1) / TB, TB>>>(p_ssd, Et, p_as, p_ad, p_e);
    gather_warp<HC1, 0><<<gwGrid, TB>>>(p_ssd, p_cnt, p_h1, p_e, b1, p_y1, N);

    // ===== Layer 2 =====
    gemm_tiled<HC2><<<dim3(gemmRows, 2), 256, GEMM_SMEM>>>(p_y1, W2, p_h2, N);
    att_kernel<HC2><<<attGrid, 256>>>(p_h2, as2, ad2, p_as, p_ad, N);
    edge_exp_kernel<<<(Et + TB - 1) / TB, TB>>>(p_ssd, Et, p_as, p_ad, p_e);
    gather_warp<HC2, 1><<<gwGrid, TB>>>(p_ssd, p_cnt, p_h2, p_e, b2, out, N);
}

// round 8
// speedup vs baseline: 2.4747x; 1.0114x over previous
#include <cuda_runtime.h>
#include <cstdint>

// Problem-shape maxima (fixed by the dataset)
#define NMAX   50000
#define EMAX   800000
#define ETMAX  (EMAX + NMAX)      // edges + self loops
#define HEADS  4
#define HC1    128                // heads * 32
#define HC2    256                // heads * 64
#define NEG_SLOPE 0.2f
#define GAT_EPS 1e-16f
#define CHUNK  256

// ---------------- scratch (static device globals; no allocation) ------------
__device__ float g_h1 [NMAX * HC1];
__device__ float g_y1 [NMAX * HC1];
__device__ float g_h2 [NMAX * HC2];
__device__ float g_asrc[NMAX * HEADS];
__device__ float g_adst[NMAX * HEADS];
__device__ float g_e   [ETMAX * HEADS];
__device__ int2  g_sd  [ETMAX];
__device__ int2  g_ssd [ETMAX];
__device__ int   g_cnt [NMAX + 1];
__device__ int   g_cur [NMAX + 1];
__device__ int   g_part[CHUNK];
__device__ int   g_is64;

// ---------------- helpers ---------------------------------------------------
__device__ __forceinline__ float lrelu(float x) {
    return x > 0.0f ? x : NEG_SLOPE * x;
}
__device__ __forceinline__ int eidx(const int* __restrict__ ei, int is64, long long pos) {
    if (is64) return (int)((const long long*)ei)[pos];
    return ei[pos];
}
__device__ __forceinline__ void fma4(float4& a, float s, float4 v) {
    a.x = fmaf(s, v.x, a.x); a.y = fmaf(s, v.y, a.y);
    a.z = fmaf(s, v.z, a.z); a.w = fmaf(s, v.w, a.w);
}
// packed f32x2 FMA: acc = x2 * w2 + acc  (both lanes)
__device__ __forceinline__ void fma_f32x2(unsigned long long& acc,
                                          unsigned long long x2,
                                          unsigned long long w2) {
    asm("fma.rn.f32x2 %0, %1, %2, %0;" : "+l"(acc) : "l"(x2), "l"(w2));
}
__device__ __forceinline__ unsigned long long pack_dup(float x) {
    unsigned long long r;
    asm("mov.b64 %0, {%1, %1};" : "=l"(r) : "r"(__float_as_uint(x)));
    return r;
}

// ---------------- dtype detection -------------------------------------------
__global__ void detect_kernel(const unsigned int* __restrict__ w, long long nWords) {
    __shared__ int s_nz;
    if (threadIdx.x == 0) s_nz = 0;
    __syncthreads();
    long long limit = nWords < 16384 ? nWords : 16384;
    int nz = 0;
    for (long long i = 1 + 2LL * threadIdx.x; i < limit; i += 2LL * blockDim.x)
        nz |= (w[i] != 0u);
    if (nz) atomicOr(&s_nz, 1);
    __syncthreads();
    if (threadIdx.x == 0) g_is64 = (s_nz == 0) ? 1 : 0;
}

// ---------------- build (src,dst) pairs + self loops, zero histogram --------
__global__ void prep_kernel(const int* __restrict__ ei, int E, int Nn,
                            int2* __restrict__ sd, int* __restrict__ cnt) {
    int e = blockIdx.x * blockDim.x + threadIdx.x;
    if (e <= Nn) cnt[e] = 0;
    int Et = E + Nn;
    if (e >= Et) return;
    int is64 = g_is64;
    int s, d;
    if (e < E) { s = eidx(ei, is64, e); d = eidx(ei, is64, (long long)E + e); }
    else       { s = d = e - E; }
    sd[e] = make_int2(s, d);
}

// ---------------- counting sort by dst --------------------------------------
__global__ void hist_kernel(const int2* __restrict__ sd, int Et, int* __restrict__ cnt) {
    int e = blockIdx.x * blockDim.x + threadIdx.x;
    if (e >= Et) return;
    atomicAdd(&cnt[sd[e].y], 1);
}

__global__ void scan_partial(const int* __restrict__ cnt, int* __restrict__ part, int Nn) {
    __shared__ int s[CHUNK];
    int i = blockIdx.x * CHUNK + threadIdx.x;
    s[threadIdx.x] = (i < Nn) ? cnt[i] : 0;
    __syncthreads();
#pragma unroll
    for (int o = CHUNK / 2; o > 0; o >>= 1) {
        if (threadIdx.x < o) s[threadIdx.x] += s[threadIdx.x + o];
        __syncthreads();
    }
    if (threadIdx.x == 0) part[blockIdx.x] = s[0];
}
__global__ void scan_tops(int* __restrict__ part, int nb, int* __restrict__ cnt, int Nn) {
    __shared__ int s[CHUNK];
    int t = threadIdx.x;
    int v = (t < nb) ? part[t] : 0;
    s[t] = v;
    __syncthreads();
#pragma unroll
    for (int o = 1; o < CHUNK; o <<= 1) {
        int u = (t >= o) ? s[t - o] : 0;
        __syncthreads();
        s[t] += u;
        __syncthreads();
    }
    if (t < nb) part[t] = s[t] - v;
    if (t == CHUNK - 1) cnt[Nn] = s[CHUNK - 1];
}
__global__ void scan_final(int* __restrict__ cnt, int* __restrict__ cur,
                           const int* __restrict__ part, int Nn) {
    __shared__ int s[CHUNK];
    int i = blockIdx.x * CHUNK + threadIdx.x;
    int t = threadIdx.x;
    int v = (i < Nn) ? cnt[i] : 0;
    s[t] = v;
    __syncthreads();
#pragma unroll
    for (int o = 1; o < CHUNK; o <<= 1) {
        int u = (t >= o) ? s[t - o] : 0;
        __syncthreads();
        s[t] += u;
        __syncthreads();
    }
    if (i < Nn) {
        int ex = part[blockIdx.x] + s[t] - v;
        cnt[i] = ex;
        cur[i] = ex;
    }
}

__global__ void place_kernel(const int2* __restrict__ sd, int Et,
                             int* __restrict__ cur, int2* __restrict__ ssd) {
    int e = blockIdx.x * blockDim.x + threadIdx.x;
    if (e >= Et) return;
    int2 p = sd[e];
    int pos = atomicAdd(&cur[p.y], 1);
    ssd[pos] = p;
}

// ---------------- tiled GEMM with packed f32x2 FMAs -------------------------
// Y[M,NOUT] = X[M,128] @ W[128,NOUT]; block tile 64 x 128, K=128 in smem,
// 256 threads, 4 rows x 8 cols (4 f32x2 col-pairs) per thread.
#define XPAD 132
template<int NOUT>
__global__ void gemm_tiled(const float* __restrict__ X,
                           const float* __restrict__ W,
                           float* __restrict__ Y, int M) {
    extern __shared__ float smem[];
    float (*Xs)[XPAD] = (float (*)[XPAD])smem;                 // [64][132]
    float (*Ws)[128]  = (float (*)[128])(smem + 64 * XPAD);    // [128][128]

    const int row0 = blockIdx.x * 64;
    const int c0   = blockIdx.y * 128;
    const int tid  = threadIdx.x;

#pragma unroll
    for (int i = 0; i < 8; i++) {
        int idx = tid + i * 256;
        int r = idx >> 5, kq = idx & 31;
        float4 v = (row0 + r < M) ? ((const float4*)X)[(size_t)(row0 + r) * 32 + kq]
                                  : make_float4(0.f, 0.f, 0.f, 0.f);
        *(float4*)&Xs[r][kq * 4] = v;
    }
#pragma unroll
    for (int i = 0; i < 16; i++) {
        int idx = tid + i * 256;
        int k = idx >> 5, cq = idx & 31;
        *(float4*)&Ws[k][cq * 4] =
            *(const float4*)&W[(size_t)k * NOUT + c0 + cq * 4];
    }
    __syncthreads();

    const int tx = tid & 15, ty = tid >> 4;
    unsigned long long acc[4][4];
#pragma unroll
    for (int ri = 0; ri < 4; ri++)
#pragma unroll
        for (int j = 0; j < 4; j++) acc[ri][j] = 0ULL;   // (+0.f, +0.f)

#pragma unroll 4
    for (int k = 0; k < 128; k++) {
        unsigned long long w2[4];
#pragma unroll
        for (int j = 0; j < 4; j++)
            w2[j] = *(const unsigned long long*)&Ws[k][tx * 8 + j * 2];
#pragma unroll
        for (int ri = 0; ri < 4; ri++) {
            unsigned long long x2 = pack_dup(Xs[ty * 4 + ri][k]);
            fma_f32x2(acc[ri][0], x2, w2[0]);
            fma_f32x2(acc[ri][1], x2, w2[1]);
            fma_f32x2(acc[ri][2], x2, w2[2]);
            fma_f32x2(acc[ri][3], x2, w2[3]);
        }
    }

#pragma unroll
    for (int ri = 0; ri < 4; ri++) {
        int r = row0 + ty * 4 + ri;
        if (r < M) {
            union { unsigned long long u[2]; float4 f; } o0, o1;
            o0.u[0] = acc[ri][0]; o0.u[1] = acc[ri][1];
            o1.u[0] = acc[ri][2]; o1.u[1] = acc[ri][3];
            *(float4*)&Y[(size_t)r * NOUT + c0 + tx * 8]     = o0.f;
            *(float4*)&Y[(size_t)r * NOUT + c0 + tx * 8 + 4] = o1.f;
        }
    }
}
#define GEMM_SMEM ((64 * XPAD + 128 * 128) * 4)

// ---------------- per-node attention coefficients (warp per node) -----------
template<int HC>
__global__ void att_kernel(const float* __restrict__ H,
                           const float* __restrict__ av_src,
                           const float* __restrict__ av_dst,
                           float* __restrict__ osrc,
                           float* __restrict__ odst, int Nn) {
    const int w    = threadIdx.x >> 5;
    const int lane = threadIdx.x & 31;
    const int n    = blockIdx.x * 8 + w;
    if (n >= Nn) return;
    constexpr int NV = HC / 128;
    const float4* h4 = (const float4*)(H + (size_t)n * HC);
    const float4* s4 = (const float4*)av_src;
    const float4* d4 = (const float4*)av_dst;
    float ps = 0.f, pd = 0.f;
#pragma unroll
    for (int v = 0; v < NV; v++) {
        int i = lane * NV + v;
        float4 h = h4[i], a = s4[i], b = d4[i];
        ps += h.x * a.x + h.y * a.y + h.z * a.z + h.w * a.w;
        pd += h.x * b.x + h.y * b.y + h.z * b.z + h.w * b.w;
    }
#pragma unroll
    for (int o = 4; o > 0; o >>= 1) {
        ps += __shfl_down_sync(0xffffffffu, ps, o);
        pd += __shfl_down_sync(0xffffffffu, pd, o);
    }
    if ((lane & 7) == 0) {
        int h = lane >> 3;
        osrc[n * HEADS + h] = ps;
        odst[n * HEADS + h] = pd;
    }
}

// ---------------- edge pass: ev = exp(lrelu(asrc+adst)) over sorted edges ---
__global__ void edge_exp_kernel(const int2* __restrict__ ssd, int Et,
                                const float* __restrict__ asrc,
                                const float* __restrict__ adst,
                                float* __restrict__ ebuf) {
    int e = blockIdx.x * blockDim.x + threadIdx.x;
    if (e >= Et) return;
    int2 p = ssd[e];
    float4 as = ((const float4*)asrc)[p.x];
    float4 ad = ((const float4*)adst)[p.y];
    float4 ev;
    ev.x = expf(lrelu(as.x + ad.x));
    ev.y = expf(lrelu(as.y + ad.y));
    ev.z = expf(lrelu(as.z + ad.z));
    ev.w = expf(lrelu(as.w + ad.w));
    ((float4*)ebuf)[e] = ev;
}

// ---------------- warp-per-node gather-reduce -------------------------------
template<int HC, int MODE>
__global__ void gather_warp(const int2* __restrict__ ssd,
                            const int*  __restrict__ off,
                            const float* __restrict__ H,
                            const float* __restrict__ ebuf,
                            const float* __restrict__ bias,
                            float* __restrict__ Y, int Nn) {
    const int n = (blockIdx.x * blockDim.x + threadIdx.x) >> 5;
    if (n >= Nn) return;
    const int lane = threadIdx.x & 31;
    const int head = lane >> 3;
    constexpr int NV = HC / 128;

    int pos = off[n];
    const int end = off[n + 1];

    float4 acc[NV];
#pragma unroll
    for (int v = 0; v < NV; v++) acc[v] = make_float4(0.f, 0.f, 0.f, 0.f);
    float sume = 0.f;

    for (; pos + 4 <= end; pos += 4) {
        int s0 = ssd[pos].x, s1 = ssd[pos + 1].x, s2 = ssd[pos + 2].x, s3 = ssd[pos + 3].x;
        float e0 = __ldg(&ebuf[(pos    ) * 4 + head]);
        float e1 = __ldg(&ebuf[(pos + 1) * 4 + head]);
        float e2 = __ldg(&ebuf[(pos + 2) * 4 + head]);
        float e3 = __ldg(&ebuf[(pos + 3) * 4 + head]);
        const float4* h0 = (const float4*)(H + (size_t)s0 * HC);
        const float4* h1 = (const float4*)(H + (size_t)s1 * HC);
        const float4* h2 = (const float4*)(H + (size_t)s2 * HC);
        const float4* h3 = (const float4*)(H + (size_t)s3 * HC);
#pragma unroll
        for (int v = 0; v < NV; v++) {
            int i = lane * NV + v;
            float4 a0 = h0[i], a1 = h1[i], a2 = h2[i], a3 = h3[i];
            fma4(acc[v], e0, a0);
            fma4(acc[v], e1, a1);
            fma4(acc[v], e2, a2);
            fma4(acc[v], e3, a3);
        }
        sume += (e0 + e1) + (e2 + e3);
    }
    for (; pos < end; pos++) {
        int s0 = ssd[pos].x;
        float e0 = __ldg(&ebuf[pos * 4 + head]);
        const float4* h0 = (const float4*)(H + (size_t)s0 * HC);
#pragma unroll
        for (int v = 0; v < NV; v++) fma4(acc[v], e0, h0[lane * NV + v]);
        sume += e0;
    }

    const float inv = 1.0f / (sume + GAT_EPS);

    if (MODE == 0) {
        float4 v = acc[0];
        float4 b4 = ((const float4*)bias)[lane];
        v.x = v.x * inv + b4.x; v.y = v.y * inv + b4.y;
        v.z = v.z * inv + b4.z; v.w = v.w * inv + b4.w;
        v.x = v.x > 0.f ? v.x : expm1f(v.x);
        v.y = v.y > 0.f ? v.y : expm1f(v.y);
        v.z = v.z > 0.f ? v.z : expm1f(v.z);
        v.w = v.w > 0.f ? v.w : expm1f(v.w);
        ((float4*)(Y + (size_t)n * HC))[lane] = v;
    } else {
        float vv[8];
#pragma unroll
        for (int v = 0; v < NV; v++) {
            vv[v * 4 + 0] = acc[v].x * inv;
            vv[v * 4 + 1] = acc[v].y * inv;
            vv[v * 4 + 2] = acc[v].z * inv;
            vv[v * 4 + 3] = acc[v].w * inv;
        }
#pragma unroll
        for (int j = 0; j < 8; j++) {
            vv[j] += __shfl_down_sync(0xffffffffu, vv[j], 16);
            vv[j] += __shfl_down_sync(0xffffffffu, vv[j], 8);
        }
        if (lane < 8) {
            float4 b0 = ((const float4*)bias)[lane * 2];
            float4 b1 = ((const float4*)bias)[lane * 2 + 1];
            float4 o0 = make_float4(0.25f * vv[0] + b0.x, 0.25f * vv[1] + b0.y,
                                    0.25f * vv[2] + b0.z, 0.25f * vv[3] + b0.w);
            float4 o1 = make_float4(0.25f * vv[4] + b1.x, 0.25f * vv[5] + b1.y,
                                    0.25f * vv[6] + b1.z, 0.25f * vv[7] + b1.w);
            float* yp = Y + (size_t)n * 64 + lane * 8;
            *(float4*)yp = o0;
            *(float4*)(yp + 4) = o1;
        }
    }
}

// ---------------- launch ----------------------------------------------------
extern "C" void kernel_launch(void* const* d_in, const int* in_sizes, int n_in,
                              void* d_out, int out_size) {
    const float* x    = (const float*)d_in[0];
    const int*   ei   = (const int*)d_in[1];
    const float* W1   = (const float*)d_in[2];
    const float* as1  = (const float*)d_in[3];
    const float* ad1  = (const float*)d_in[4];
    const float* b1   = (const float*)d_in[5];
    const float* W2   = (const float*)d_in[6];
    const float* as2  = (const float*)d_in[7];
    const float* ad2  = (const float*)d_in[8];
    const float* b2   = (const float*)d_in[9];
    float*       out  = (float*)d_out;

    const int N  = in_sizes[0] / 128;
    const int E  = in_sizes[1] / 2;
    const int Et = E + N;

    float *p_h1, *p_y1, *p_h2, *p_as, *p_ad, *p_e;
    int2 *p_sd, *p_ssd;
    int *p_cnt, *p_cur, *p_part;
    cudaGetSymbolAddress((void**)&p_h1,  g_h1);
    cudaGetSymbolAddress((void**)&p_y1,  g_y1);
    cudaGetSymbolAddress((void**)&p_h2,  g_h2);
    cudaGetSymbolAddress((void**)&p_as,  g_asrc);
    cudaGetSymbolAddress((void**)&p_ad,  g_adst);
    cudaGetSymbolAddress((void**)&p_e,   g_e);
    cudaGetSymbolAddress((void**)&p_sd,  g_sd);
    cudaGetSymbolAddress((void**)&p_ssd, g_ssd);
    cudaGetSymbolAddress((void**)&p_cnt, g_cnt);
    cudaGetSymbolAddress((void**)&p_cur, g_cur);
    cudaGetSymbolAddress((void**)&p_part, g_part);

    static int smem_set = 0;
    if (!smem_set) {
        cudaFuncSetAttribute(gemm_tiled<HC1>, cudaFuncAttributeMaxDynamicSharedMemorySize, GEMM_SMEM);
        cudaFuncSetAttribute(gemm_tiled<HC2>, cudaFuncAttributeMaxDynamicSharedMemorySize, GEMM_SMEM);
        smem_set = 1;
    }

    const int TB = 256;
    const int gemmRows = (N + 63) / 64;
    const int attGrid  = (N + 7) / 8;
    const int nb       = (N + CHUNK - 1) / CHUNK;
    const int gwGrid   = (N * 32 + TB - 1) / TB;   // warp per node

    // ---- edge preprocessing: dtype sniff + counting sort by dst ----
    detect_kernel<<<1, 256>>>((const unsigned int*)ei, (long long)in_sizes[1] * 2);
    prep_kernel<<<(Et + TB - 1) / TB, TB>>>(ei, E, N, p_sd, p_cnt);
    hist_kernel<<<(Et + TB - 1) / TB, TB>>>(p_sd, Et, p_cnt);
    scan_partial<<<nb, CHUNK>>>(p_cnt, p_part, N);
    scan_tops<<<1, CHUNK>>>(p_part, nb, p_cnt, N);
    scan_final<<<nb, CHUNK>>>(p_cnt, p_cur, p_part, N);
    place_kernel<<<(Et + TB - 1) / TB, TB>>>(p_sd, Et, p_cur, p_ssd);

    // ===== Layer 1 =====
    gemm_tiled<HC1><<<dim3(gemmRows, 1), 256, GEMM_SMEM>>>(x, W1, p_h1, N);
    att_kernel<HC1><<<attGrid, 256>>>(p_h1, as1, ad1, p_as, p_ad, N);
    edge_exp_kernel<<<(Et + TB - 1) / TB, TB>>>(p_ssd, Et, p_as, p_ad, p_e);
    gather_warp<HC1, 0><<<gwGrid, TB>>>(p_ssd, p_cnt, p_h1, p_e, b1, p_y1, N);

    // ===== Layer 2 =====
    gemm_tiled<HC2><<<dim3(gemmRows, 2), 256, GEMM_SMEM>>>(p_y1, W2, p_h2, N);
    att_kernel<HC2><<<attGrid, 256>>>(p_h2, as2, ad2, p_as, p_ad, N);
    edge_exp_kernel<<<(Et + TB - 1) / TB, TB>>>(p_ssd, Et, p_as, p_ad, p_e);
    gather_warp<HC2, 1><<<gwGrid, TB>>>(p_ssd, p_cnt, p_h2, p_e, b2, out, N);
}

// round 9
// speedup vs baseline: 2.5630x; 1.0357x over previous
#include <cuda_runtime.h>
#include <cstdint>

// Problem-shape maxima (fixed by the dataset)
#define NMAX   50000
#define EMAX   800000
#define ETMAX  (EMAX + NMAX)      // edges + self loops
#define HEADS  4
#define HC1    128                // heads * 32
#define HC2    256                // heads * 64
#define NEG_SLOPE 0.2f
#define GAT_EPS 1e-16f
#define CHUNK  256

// ---------------- scratch (static device globals; no allocation) ------------
__device__ float g_h1 [NMAX * HC1];
__device__ float g_y1 [NMAX * HC1];
__device__ float g_h2 [NMAX * HC2];
__device__ float g_asrc[NMAX * HEADS];
__device__ float g_adst[NMAX * HEADS];
__device__ float g_e   [ETMAX * HEADS];
__device__ int2  g_sd  [ETMAX];
__device__ int2  g_ssd [ETMAX];
__device__ int   g_cnt [NMAX + 1];
__device__ int   g_cur [NMAX + 1];
__device__ int   g_part[CHUNK];
__device__ int   g_is64;

// ---------------- helpers ---------------------------------------------------
__device__ __forceinline__ float lrelu(float x) {
    return x > 0.0f ? x : NEG_SLOPE * x;
}
__device__ __forceinline__ int eidx(const int* __restrict__ ei, int is64, long long pos) {
    if (is64) return (int)((const long long*)ei)[pos];
    return ei[pos];
}
__device__ __forceinline__ void fma4(float4& a, float s, float4 v) {
    a.x = fmaf(s, v.x, a.x); a.y = fmaf(s, v.y, a.y);
    a.z = fmaf(s, v.z, a.z); a.w = fmaf(s, v.w, a.w);
}
// packed f32x2 FMA: acc = x2 * w2 + acc  (both lanes)
__device__ __forceinline__ void fma_f32x2(unsigned long long& acc,
                                          unsigned long long x2,
                                          unsigned long long w2) {
    asm("fma.rn.f32x2 %0, %1, %2, %0;" : "+l"(acc) : "l"(x2), "l"(w2));
}
__device__ __forceinline__ unsigned long long pack_dup(float x) {
    unsigned long long r;
    asm("mov.b64 %0, {%1, %1};" : "=l"(r) : "r"(__float_as_uint(x)));
    return r;
}

// ---------------- dtype detection -------------------------------------------
__global__ void detect_kernel(const unsigned int* __restrict__ w, long long nWords) {
    __shared__ int s_nz;
    if (threadIdx.x == 0) s_nz = 0;
    __syncthreads();
    long long limit = nWords < 16384 ? nWords : 16384;
    int nz = 0;
    for (long long i = 1 + 2LL * threadIdx.x; i < limit; i += 2LL * blockDim.x)
        nz |= (w[i] != 0u);
    if (nz) atomicOr(&s_nz, 1);
    __syncthreads();
    if (threadIdx.x == 0) g_is64 = (s_nz == 0) ? 1 : 0;
}

// ---------------- build (src,dst) pairs + self loops, zero histogram --------
__global__ void prep_kernel(const int* __restrict__ ei, int E, int Nn,
                            int2* __restrict__ sd, int* __restrict__ cnt) {
    int e = blockIdx.x * blockDim.x + threadIdx.x;
    if (e <= Nn) cnt[e] = 0;
    int Et = E + Nn;
    if (e >= Et) return;
    int is64 = g_is64;
    int s, d;
    if (e < E) { s = eidx(ei, is64, e); d = eidx(ei, is64, (long long)E + e); }
    else       { s = d = e - E; }
    sd[e] = make_int2(s, d);
}

// ---------------- counting sort by dst --------------------------------------
__global__ void hist_kernel(const int2* __restrict__ sd, int Et, int* __restrict__ cnt) {
    int e = blockIdx.x * blockDim.x + threadIdx.x;
    if (e >= Et) return;
    atomicAdd(&cnt[sd[e].y], 1);
}

__global__ void scan_partial(const int* __restrict__ cnt, int* __restrict__ part, int Nn) {
    __shared__ int s[CHUNK];
    int i = blockIdx.x * CHUNK + threadIdx.x;
    s[threadIdx.x] = (i < Nn) ? cnt[i] : 0;
    __syncthreads();
#pragma unroll
    for (int o = CHUNK / 2; o > 0; o >>= 1) {
        if (threadIdx.x < o) s[threadIdx.x] += s[threadIdx.x + o];
        __syncthreads();
    }
    if (threadIdx.x == 0) part[blockIdx.x] = s[0];
}
__global__ void scan_tops(int* __restrict__ part, int nb, int* __restrict__ cnt, int Nn) {
    __shared__ int s[CHUNK];
    int t = threadIdx.x;
    int v = (t < nb) ? part[t] : 0;
    s[t] = v;
    __syncthreads();
#pragma unroll
    for (int o = 1; o < CHUNK; o <<= 1) {
        int u = (t >= o) ? s[t - o] : 0;
        __syncthreads();
        s[t] += u;
        __syncthreads();
    }
    if (t < nb) part[t] = s[t] - v;
    if (t == CHUNK - 1) cnt[Nn] = s[CHUNK - 1];
}
__global__ void scan_final(int* __restrict__ cnt, int* __restrict__ cur,
                           const int* __restrict__ part, int Nn) {
    __shared__ int s[CHUNK];
    int i = blockIdx.x * CHUNK + threadIdx.x;
    int t = threadIdx.x;
    int v = (i < Nn) ? cnt[i] : 0;
    s[t] = v;
    __syncthreads();
#pragma unroll
    for (int o = 1; o < CHUNK; o <<= 1) {
        int u = (t >= o) ? s[t - o] : 0;
        __syncthreads();
        s[t] += u;
        __syncthreads();
    }
    if (i < Nn) {
        int ex = part[blockIdx.x] + s[t] - v;
        cnt[i] = ex;
        cur[i] = ex;
    }
}

__global__ void place_kernel(const int2* __restrict__ sd, int Et,
                             int* __restrict__ cur, int2* __restrict__ ssd) {
    int e = blockIdx.x * blockDim.x + threadIdx.x;
    if (e >= Et) return;
    int2 p = sd[e];
    int pos = atomicAdd(&cur[p.y], 1);
    ssd[pos] = p;
}

// ---------------- tiled GEMM with packed f32x2 FMAs, K-split W stage --------
// Y[M,NOUT] = X[M,128] @ W[128,NOUT]; block tile 64 x 128. W staged in two
// K-halves (Ws[64][128]) so smem = 66KB -> 3 blocks/SM (24 warps).
#define XPAD 132
template<int NOUT>
__global__ void gemm_tiled(const float* __restrict__ X,
                           const float* __restrict__ W,
                           float* __restrict__ Y, int M) {
    extern __shared__ float smem[];
    float (*Xs)[XPAD] = (float (*)[XPAD])smem;                 // [64][132]
    float (*Ws)[128]  = (float (*)[128])(smem + 64 * XPAD);    // [64][128]

    const int row0 = blockIdx.x * 64;
    const int c0   = blockIdx.y * 128;
    const int tid  = threadIdx.x;
    const int tx = tid & 15, ty = tid >> 4;

#pragma unroll
    for (int i = 0; i < 8; i++) {
        int idx = tid + i * 256;
        int r = idx >> 5, kq = idx & 31;
        float4 v = (row0 + r < M) ? ((const float4*)X)[(size_t)(row0 + r) * 32 + kq]
                                  : make_float4(0.f, 0.f, 0.f, 0.f);
        *(float4*)&Xs[r][kq * 4] = v;
    }

    unsigned long long acc[4][4];
#pragma unroll
    for (int ri = 0; ri < 4; ri++)
#pragma unroll
        for (int j = 0; j < 4; j++) acc[ri][j] = 0ULL;

#pragma unroll
    for (int half = 0; half < 2; half++) {
        // stage 64 K-rows of W
        __syncthreads();
#pragma unroll
        for (int i = 0; i < 8; i++) {
            int idx = tid + i * 256;
            int k = idx >> 5, cq = idx & 31;
            *(float4*)&Ws[k][cq * 4] =
                *(const float4*)&W[(size_t)(half * 64 + k) * NOUT + c0 + cq * 4];
        }
        __syncthreads();

#pragma unroll 4
        for (int kk = 0; kk < 64; kk++) {
            int k = half * 64 + kk;
            unsigned long long w2[4];
#pragma unroll
            for (int j = 0; j < 4; j++)
                w2[j] = *(const unsigned long long*)&Ws[kk][tx * 8 + j * 2];
#pragma unroll
            for (int ri = 0; ri < 4; ri++) {
                unsigned long long x2 = pack_dup(Xs[ty * 4 + ri][k]);
                fma_f32x2(acc[ri][0], x2, w2[0]);
                fma_f32x2(acc[ri][1], x2, w2[1]);
                fma_f32x2(acc[ri][2], x2, w2[2]);
                fma_f32x2(acc[ri][3], x2, w2[3]);
            }
        }
    }

#pragma unroll
    for (int ri = 0; ri < 4; ri++) {
        int r = row0 + ty * 4 + ri;
        if (r < M) {
            union { unsigned long long u[2]; float4 f; } o0, o1;
            o0.u[0] = acc[ri][0]; o0.u[1] = acc[ri][1];
            o1.u[0] = acc[ri][2]; o1.u[1] = acc[ri][3];
            *(float4*)&Y[(size_t)r * NOUT + c0 + tx * 8]     = o0.f;
            *(float4*)&Y[(size_t)r * NOUT + c0 + tx * 8 + 4] = o1.f;
        }
    }
}
#define GEMM_SMEM ((64 * XPAD + 64 * 128) * 4)

// ---------------- per-node attention coefficients (warp per node) -----------
template<int HC>
__global__ void att_kernel(const float* __restrict__ H,
                           const float* __restrict__ av_src,
                           const float* __restrict__ av_dst,
                           float* __restrict__ osrc,
                           float* __restrict__ odst, int Nn) {
    const int w    = threadIdx.x >> 5;
    const int lane = threadIdx.x & 31;
    const int n    = blockIdx.x * 8 + w;
    if (n >= Nn) return;
    constexpr int NV = HC / 128;
    const float4* h4 = (const float4*)(H + (size_t)n * HC);
    const float4* s4 = (const float4*)av_src;
    const float4* d4 = (const float4*)av_dst;
    float ps = 0.f, pd = 0.f;
#pragma unroll
    for (int v = 0; v < NV; v++) {
        int i = lane * NV + v;
        float4 h = h4[i], a = s4[i], b = d4[i];
        ps += h.x * a.x + h.y * a.y + h.z * a.z + h.w * a.w;
        pd += h.x * b.x + h.y * b.y + h.z * b.z + h.w * b.w;
    }
#pragma unroll
    for (int o = 4; o > 0; o >>= 1) {
        ps += __shfl_down_sync(0xffffffffu, ps, o);
        pd += __shfl_down_sync(0xffffffffu, pd, o);
    }
    if ((lane & 7) == 0) {
        int h = lane >> 3;
        osrc[n * HEADS + h] = ps;
        odst[n * HEADS + h] = pd;
    }
}

// ---------------- edge pass: ev = exp(lrelu(asrc+adst)) over sorted edges ---
__global__ void edge_exp_kernel(const int2* __restrict__ ssd, int Et,
                                const float* __restrict__ asrc,
                                const float* __restrict__ adst,
                                float* __restrict__ ebuf) {
    int e = blockIdx.x * blockDim.x + threadIdx.x;
    if (e >= Et) return;
    int2 p = ssd[e];
    float4 as = ((const float4*)asrc)[p.x];
    float4 ad = ((const float4*)adst)[p.y];
    float4 ev;
    ev.x = expf(lrelu(as.x + ad.x));
    ev.y = expf(lrelu(as.y + ad.y));
    ev.z = expf(lrelu(as.z + ad.z));
    ev.w = expf(lrelu(as.w + ad.w));
    ((float4*)ebuf)[e] = ev;
}

// ---------------- warp-per-node gather-reduce -------------------------------
template<int HC, int MODE>
__global__ void gather_warp(const int2* __restrict__ ssd,
                            const int*  __restrict__ off,
                            const float* __restrict__ H,
                            const float* __restrict__ ebuf,
                            const float* __restrict__ bias,
                            float* __restrict__ Y, int Nn) {
    const int n = (blockIdx.x * blockDim.x + threadIdx.x) >> 5;
    if (n >= Nn) return;
    const int lane = threadIdx.x & 31;
    const int head = lane >> 3;
    constexpr int NV = HC / 128;

    int pos = off[n];
    const int end = off[n + 1];

    float4 acc[NV];
#pragma unroll
    for (int v = 0; v < NV; v++) acc[v] = make_float4(0.f, 0.f, 0.f, 0.f);
    float sume = 0.f;

    for (; pos + 4 <= end; pos += 4) {
        int s0 = ssd[pos].x, s1 = ssd[pos + 1].x, s2 = ssd[pos + 2].x, s3 = ssd[pos + 3].x;
        float e0 = __ldg(&ebuf[(pos    ) * 4 + head]);
        float e1 = __ldg(&ebuf[(pos + 1) * 4 + head]);
        float e2 = __ldg(&ebuf[(pos + 2) * 4 + head]);
        float e3 = __ldg(&ebuf[(pos + 3) * 4 + head]);
        const float4* h0 = (const float4*)(H + (size_t)s0 * HC);
        const float4* h1 = (const float4*)(H + (size_t)s1 * HC);
        const float4* h2 = (const float4*)(H + (size_t)s2 * HC);
        const float4* h3 = (const float4*)(H + (size_t)s3 * HC);
#pragma unroll
        for (int v = 0; v < NV; v++) {
            int i = lane * NV + v;
            float4 a0 = h0[i], a1 = h1[i], a2 = h2[i], a3 = h3[i];
            fma4(acc[v], e0, a0);
            fma4(acc[v], e1, a1);
            fma4(acc[v], e2, a2);
            fma4(acc[v], e3, a3);
        }
        sume += (e0 + e1) + (e2 + e3);
    }
    for (; pos < end; pos++) {
        int s0 = ssd[pos].x;
        float e0 = __ldg(&ebuf[pos * 4 + head]);
        const float4* h0 = (const float4*)(H + (size_t)s0 * HC);
#pragma unroll
        for (int v = 0; v < NV; v++) fma4(acc[v], e0, h0[lane * NV + v]);
        sume += e0;
    }

    const float inv = 1.0f / (sume + GAT_EPS);

    if (MODE == 0) {
        float4 v = acc[0];
        float4 b4 = ((const float4*)bias)[lane];
        v.x = v.x * inv + b4.x; v.y = v.y * inv + b4.y;
        v.z = v.z * inv + b4.z; v.w = v.w * inv + b4.w;
        v.x = v.x > 0.f ? v.x : expm1f(v.x);
        v.y = v.y > 0.f ? v.y : expm1f(v.y);
        v.z = v.z > 0.f ? v.z : expm1f(v.z);
        v.w = v.w > 0.f ? v.w : expm1f(v.w);
        ((float4*)(Y + (size_t)n * HC))[lane] = v;
    } else {
        float vv[8];
#pragma unroll
        for (int v = 0; v < NV; v++) {
            vv[v * 4 + 0] = acc[v].x * inv;
            vv[v * 4 + 1] = acc[v].y * inv;
            vv[v * 4 + 2] = acc[v].z * inv;
            vv[v * 4 + 3] = acc[v].w * inv;
        }
#pragma unroll
        for (int j = 0; j < 8; j++) {
            vv[j] += __shfl_down_sync(0xffffffffu, vv[j], 16);
            vv[j] += __shfl_down_sync(0xffffffffu, vv[j], 8);
        }
        if (lane < 8) {
            float4 b0 = ((const float4*)bias)[lane * 2];
            float4 b1 = ((const float4*)bias)[lane * 2 + 1];
            float4 o0 = make_float4(0.25f * vv[0] + b0.x, 0.25f * vv[1] + b0.y,
                                    0.25f * vv[2] + b0.z, 0.25f * vv[3] + b0.w);
            float4 o1 = make_float4(0.25f * vv[4] + b1.x, 0.25f * vv[5] + b1.y,
                                    0.25f * vv[6] + b1.z, 0.25f * vv[7] + b1.w);
            float* yp = Y + (size_t)n * 64 + lane * 8;
            *(float4*)yp = o0;
            *(float4*)(yp + 4) = o1;
        }
    }
}

// ---------------- launch ----------------------------------------------------
extern "C" void kernel_launch(void* const* d_in, const int* in_sizes, int n_in,
                              void* d_out, int out_size) {
    const float* x    = (const float*)d_in[0];
    const int*   ei   = (const int*)d_in[1];
    const float* W1   = (const float*)d_in[2];
    const float* as1  = (const float*)d_in[3];
    const float* ad1  = (const float*)d_in[4];
    const float* b1   = (const float*)d_in[5];
    const float* W2   = (const float*)d_in[6];
    const float* as2  = (const float*)d_in[7];
    const float* ad2  = (const float*)d_in[8];
    const float* b2   = (const float*)d_in[9];
    float*       out  = (float*)d_out;

    const int N  = in_sizes[0] / 128;
    const int E  = in_sizes[1] / 2;
    const int Et = E + N;

    float *p_h1, *p_y1, *p_h2, *p_as, *p_ad, *p_e;
    int2 *p_sd, *p_ssd;
    int *p_cnt, *p_cur, *p_part;
    cudaGetSymbolAddress((void**)&p_h1,  g_h1);
    cudaGetSymbolAddress((void**)&p_y1,  g_y1);
    cudaGetSymbolAddress((void**)&p_h2,  g_h2);
    cudaGetSymbolAddress((void**)&p_as,  g_asrc);
    cudaGetSymbolAddress((void**)&p_ad,  g_adst);
    cudaGetSymbolAddress((void**)&p_e,   g_e);
    cudaGetSymbolAddress((void**)&p_sd,  g_sd);
    cudaGetSymbolAddress((void**)&p_ssd, g_ssd);
    cudaGetSymbolAddress((void**)&p_cnt, g_cnt);
    cudaGetSymbolAddress((void**)&p_cur, g_cur);
    cudaGetSymbolAddress((void**)&p_part, g_part);

    static int smem_set = 0;
    if (!smem_set) {
        cudaFuncSetAttribute(gemm_tiled<HC1>, cudaFuncAttributeMaxDynamicSharedMemorySize, GEMM_SMEM);
        cudaFuncSetAttribute(gemm_tiled<HC2>, cudaFuncAttributeMaxDynamicSharedMemorySize, GEMM_SMEM);
        smem_set = 1;
    }

    const int TB = 256;
    const int gemmRows = (N + 63) / 64;
    const int attGrid  = (N + 7) / 8;
    const int nb       = (N + CHUNK - 1) / CHUNK;
    const int gwGrid   = (N * 32 + TB - 1) / TB;   // warp per node

    // ---- edge preprocessing: dtype sniff + counting sort by dst ----
    detect_kernel<<<1, 256>>>((const unsigned int*)ei, (long long)in_sizes[1] * 2);
    prep_kernel<<<(Et + TB - 1) / TB, TB>>>(ei, E, N, p_sd, p_cnt);
    hist_kernel<<<(Et + TB - 1) / TB, TB>>>(p_sd, Et, p_cnt);
    scan_partial<<<nb, CHUNK>>>(p_cnt, p_part, N);
    scan_tops<<<1, CHUNK>>>(p_part, nb, p_cnt, N);
    scan_final<<<nb, CHUNK>>>(p_cnt, p_cur, p_part, N);
    place_kernel<<<(Et + TB - 1) / TB, TB>>>(p_sd, Et, p_cur, p_ssd);

    // ===== Layer 1 =====
    gemm_tiled<HC1><<<dim3(gemmRows, 1), 256, GEMM_SMEM>>>(x, W1, p_h1, N);
    att_kernel<HC1><<<attGrid, 256>>>(p_h1, as1, ad1, p_as, p_ad, N);
    edge_exp_kernel<<<(Et + TB - 1) / TB, TB>>>(p_ssd, Et, p_as, p_ad, p_e);
    gather_warp<HC1, 0><<<gwGrid, TB>>>(p_ssd, p_cnt, p_h1, p_e, b1, p_y1, N);

    // ===== Layer 2 =====
    gemm_tiled<HC2><<<dim3(gemmRows, 2), 256, GEMM_SMEM>>>(p_y1, W2, p_h2, N);
    att_kernel<HC2><<<attGrid, 256>>>(p_h2, as2, ad2, p_as, p_ad, N);
    edge_exp_kernel<<<(Et + TB - 1) / TB, TB>>>(p_ssd, Et, p_as, p_ad, p_e);
    gather_warp<HC2, 1><<<gwGrid, TB>>>(p_ssd, p_cnt, p_h2, p_e, b2, out, N);
}